// round 13
// baseline (speedup 1.0000x reference)
#include <cuda_runtime.h>
#include <cstdint>

#define N_USERS 100000
#define N_ITEMS 60000
#define N_NODES 160000
#define D 64
#define D4 16              // D in float4 units
#define USER_LIM (N_USERS * D4)   // pre-scaled col threshold (1.6M)
#define NNZ 1280000
#define EPS 0.1f
#define SCAN_T 1024
#define QUADS (N_NODES / 4)                       // 40000
#define NB_SCAN ((QUADS + SCAN_T - 1) / SCAN_T)   // 40

// ---------------- scratch (static device globals; no allocation) -------------
__device__ __align__(16) int g_cnt[N_NODES];     // zero-init invariant
__device__ __align__(16) int g_rowptr[N_NODES + 4];
__device__ __align__(16) int g_cursor[N_NODES];
__device__ unsigned long long g_state[64];       // decoupled-lookback state
__device__ int2  g_edges[NNZ];                   // packed (col*D4, val-bits)
__device__ float g_ego1[(size_t)N_NODES * D];
__device__ float g_ego2[(size_t)N_NODES * D];

// ---------------- histogram: 4 edges/thread; also resets state + rowptr[N] ---
__global__ void k_hist(const int4* __restrict__ rows4) {
    int t = blockIdx.x * blockDim.x + threadIdx.x;
    if (blockIdx.x == 0) {
        if (threadIdx.x < NB_SCAN) g_state[threadIdx.x] = 0ULL;
        if (threadIdx.x == NB_SCAN) g_rowptr[N_NODES] = NNZ;   // known constant
    }
    if (t < NNZ / 4) {
        const int4 r = __ldcs(&rows4[t]);
        atomicAdd(&g_cnt[r.x], 1);
        atomicAdd(&g_cnt[r.y], 1);
        atomicAdd(&g_cnt[r.z], 1);
        atomicAdd(&g_cnt[r.w], 1);
    }
}

// ---------------- single-pass exclusive scan, 4 nodes/thread -----------------
__global__ void k_scan() {
    __shared__ int wsum[32];
    __shared__ int s_running;
    const int bid  = blockIdx.x;
    const int t    = bid * SCAN_T + threadIdx.x;   // quad index
    const int lane = threadIdx.x & 31;
    const int wid  = threadIdx.x >> 5;

    int4 v = make_int4(0, 0, 0, 0);
    if (t < QUADS) {
        v = *reinterpret_cast<int4*>(&g_cnt[t * 4]);
        *reinterpret_cast<int4*>(&g_cnt[t * 4]) = make_int4(0, 0, 0, 0);
    }
    const int tot = v.x + v.y + v.z + v.w;

    int s = tot;
    #pragma unroll
    for (int d = 1; d < 32; d <<= 1) {
        int u = __shfl_up_sync(0xffffffffu, s, d);
        if (lane >= d) s += u;
    }
    if (lane == 31) wsum[wid] = s;
    __syncthreads();
    if (wid == 0) {
        int ws = wsum[lane];
        #pragma unroll
        for (int d = 1; d < 32; d <<= 1) {
            int u = __shfl_up_sync(0xffffffffu, ws, d);
            if (lane >= d) ws += u;
        }
        wsum[lane] = ws;
    }
    __syncthreads();
    const int incl  = s + (wid ? wsum[wid - 1] : 0);
    const int total = wsum[31];

    if (threadIdx.x == 0) {
        unsigned long long pk = ((bid == 0) ? (2ULL << 32) : (1ULL << 32))
                                | (unsigned)total;
        __threadfence();
        atomicExch(&g_state[bid], pk);
        if (bid == 0) s_running = 0;
    }

    if (wid == 0 && bid > 0) {
        int running = 0;
        int pb = bid - 1;
        while (true) {
            int idx = pb - lane;
            unsigned long long st = 0ULL;
            if (idx >= 0) {
                do {
                    st = *(volatile unsigned long long*)&g_state[idx];
                } while ((st >> 32) == 0ULL);
            }
            unsigned pm = __ballot_sync(0xffffffffu, (idx >= 0) && ((st >> 32) == 2ULL));
            int val = (idx >= 0) ? (int)(st & 0xffffffffULL) : 0;
            if (pm) {
                int fp = __ffs(pm) - 1;
                int contrib = (lane <= fp) ? val : 0;
                #pragma unroll
                for (int m = 16; m; m >>= 1) contrib += __shfl_xor_sync(0xffffffffu, contrib, m);
                running += contrib;
                break;
            } else {
                int contrib = val;
                #pragma unroll
                for (int m = 16; m; m >>= 1) contrib += __shfl_xor_sync(0xffffffffu, contrib, m);
                running += contrib;
                pb -= 32;
            }
        }
        if (lane == 0) {
            __threadfence();
            atomicExch(&g_state[bid], (2ULL << 32) | (unsigned)(total + running));
            s_running = running;
        }
    }
    __syncthreads();

    if (t < QUADS) {
        const int r0 = incl - tot + s_running;
        const int r1 = r0 + v.x;
        const int r2 = r1 + v.y;
        const int r3 = r2 + v.z;
        const int4 rp = make_int4(r0, r1, r2, r3);
        *reinterpret_cast<int4*>(&g_rowptr[t * 4]) = rp;
        *reinterpret_cast<int4*>(&g_cursor[t * 4]) = rp;
    }
}

// ---------------- scatter: 4 edges/thread, stores PRE-SCALED col*D4 ----------
__global__ void k_scatter(const int4* __restrict__ rows4,
                          const int4* __restrict__ cols4,
                          const float4* __restrict__ vals4) {
    int t = blockIdx.x * blockDim.x + threadIdx.x;
    if (t < NNZ / 4) {
        const int4   r = __ldcs(&rows4[t]);
        const int4   c = __ldcs(&cols4[t]);
        const float4 v = __ldcs(&vals4[t]);
        int p;
        p = atomicAdd(&g_cursor[r.x], 1); g_edges[p] = make_int2(c.x * D4, __float_as_int(v.x));
        p = atomicAdd(&g_cursor[r.y], 1); g_edges[p] = make_int2(c.y * D4, __float_as_int(v.y));
        p = atomicAdd(&g_cursor[r.z], 1); g_edges[p] = make_int2(c.z * D4, __float_as_int(v.z));
        p = atomicAdd(&g_cursor[r.w], 1); g_edges[p] = make_int2(c.w * D4, __float_as_int(v.w));
    }
}

// ---------------- fused SpMM + noise-perturb + epilogue ----------------------
// R9 loop, untouched structure. GATHER: pre-scaled offsets (no IMAD); SPLIT
// removes the user/item base select for layers 1/2 (single contiguous x).
template <int K, bool SPLIT>
__global__ void __launch_bounds__(256, 7)
k_spmm(const float4* __restrict__ xu,
       const float4* __restrict__ xi_adj,          // xi - USER_LIM (SPLIT only)
       const float4* __restrict__ noise,           // offset to layer K
       const float4* __restrict__ prevA,           // K==2: ego1
       const float4* __restrict__ prevB,           // K==2: ego2
       float4* __restrict__ yout,                  // K==0/1
       float4* __restrict__ out4)                  // d_out as float4
{
    const int gw   = (blockIdx.x * blockDim.x + threadIdx.x) >> 5;
    const int lane = threadIdx.x & 31;
    const int half = lane >> 4;
    const unsigned fl = lane & 15;
    const int row  = gw * 2 + half;
    if (row >= N_NODES) return;

    int p   = __ldg(&g_rowptr[row]);
    int end = __ldg(&g_rowptr[row + 1]);

    float4 acc = make_float4(0.f, 0.f, 0.f, 0.f);

    #define GATHER(e) (SPLIT \
        ? __ldg((((e).x < USER_LIM) ? xu : xi_adj) + ((unsigned)(e).x + fl)) \
        : __ldg(xu + ((unsigned)(e).x + fl)))
    #define FMA4(v, t) do { \
        acc.x = fmaf((v), (t).x, acc.x); \
        acc.y = fmaf((v), (t).y, acc.y); \
        acc.z = fmaf((v), (t).z, acc.z); \
        acc.w = fmaf((v), (t).w, acc.w); } while (0)

    if (p + 4 <= end) {
        int2 e0 = __ldg(&g_edges[p + 0]);
        int2 e1 = __ldg(&g_edges[p + 1]);
        int2 e2 = __ldg(&g_edges[p + 2]);
        int2 e3 = __ldg(&g_edges[p + 3]);
        for (; p + 8 <= end; p += 4) {
            const float4 t0 = GATHER(e0);
            const float4 t1 = GATHER(e1);
            const float4 t2 = GATHER(e2);
            const float4 t3 = GATHER(e3);
            const int2 n0 = __ldg(&g_edges[p + 4]);
            const int2 n1 = __ldg(&g_edges[p + 5]);
            const int2 n2 = __ldg(&g_edges[p + 6]);
            const int2 n3 = __ldg(&g_edges[p + 7]);
            FMA4(__int_as_float(e0.y), t0);
            FMA4(__int_as_float(e1.y), t1);
            FMA4(__int_as_float(e2.y), t2);
            FMA4(__int_as_float(e3.y), t3);
            e0 = n0; e1 = n1; e2 = n2; e3 = n3;
        }
        const float4 t0 = GATHER(e0);
        const float4 t1 = GATHER(e1);
        const float4 t2 = GATHER(e2);
        const float4 t3 = GATHER(e3);
        FMA4(__int_as_float(e0.y), t0);
        FMA4(__int_as_float(e1.y), t1);
        FMA4(__int_as_float(e2.y), t2);
        FMA4(__int_as_float(e3.y), t3);
        p += 4;
    }
    for (; p < end; ++p) {
        const int2 e0 = __ldg(&g_edges[p]);
        const float4 t0 = GATHER(e0);
        FMA4(__int_as_float(e0.y), t0);
    }
    #undef GATHER
    #undef FMA4

    const size_t off = (size_t)row * D4 + fl;
    const float4 nk  = __ldcs(noise + off);

    float ss = nk.x * nk.x + nk.y * nk.y + nk.z * nk.z + nk.w * nk.w;
    #pragma unroll
    for (int m = 8; m; m >>= 1) ss += __shfl_xor_sync(0xffffffffu, ss, m);
    const float inv = EPS / fmaxf(sqrtf(ss), 1e-12f);
    float4 r = acc;
    r.x += ((acc.x > 0.f) ? 1.f : ((acc.x < 0.f) ? -1.f : 0.f)) * nk.x * inv;
    r.y += ((acc.y > 0.f) ? 1.f : ((acc.y < 0.f) ? -1.f : 0.f)) * nk.y * inv;
    r.z += ((acc.z > 0.f) ? 1.f : ((acc.z < 0.f) ? -1.f : 0.f)) * nk.z * inv;
    r.w += ((acc.w > 0.f) ? 1.f : ((acc.w < 0.f) ? -1.f : 0.f)) * nk.w * inv;

    if (K == 0) {
        yout[off] = r;                                     // ego1 (reused next layer)
        __stcs(out4 + (size_t)N_NODES * D4 + off, r);      // CL region: stream out
    } else if (K == 1) {
        yout[off] = r;                                     // ego2
    } else {
        const float4 pa = __ldcs(prevA + off);             // ego1: last use
        const float4 pb = __ldg(prevB + off);              // ego2: L2-hot
        const float third = 1.f / 3.f;
        float4 f;
        f.x = (pa.x + pb.x + r.x) * third;
        f.y = (pa.y + pb.y + r.y) * third;
        f.z = (pa.z + pb.z + r.z) * third;
        f.w = (pa.w + pb.w + r.w) * third;
        __stcs(out4 + off, f);                             // final region: stream out
    }
}

// ---------------- launch ------------------------------------------------------
extern "C" void kernel_launch(void* const* d_in, const int* in_sizes, int n_in,
                              void* d_out, int out_size) {
    const float* user_emb = (const float*)d_in[0];
    const float* item_emb = (const float*)d_in[1];
    const float* adj_vals = (const float*)d_in[2];
    const float* noise    = (const float*)d_in[3];
    const int*   adj_rows = (const int*)d_in[4];
    const int*   adj_cols = (const int*)d_in[5];
    float4* out4 = (float4*)d_out;

    // --- build CSR from COO ---
    const int eth = NNZ / 4;                               // 320000
    k_hist<<<(eth + 255) / 256, 256>>>((const int4*)adj_rows);
    k_scan<<<NB_SCAN, SCAN_T>>>();
    k_scatter<<<(eth + 255) / 256, 256>>>((const int4*)adj_rows,
                                          (const int4*)adj_cols,
                                          (const float4*)adj_vals);

    static float4* ego1 = nullptr;
    static float4* ego2 = nullptr;
    if (!ego1) {
        void* p;
        cudaGetSymbolAddress(&p, g_ego1); ego1 = (float4*)p;
        cudaGetSymbolAddress(&p, g_ego2); ego2 = (float4*)p;
    }

    const float4* noise4 = (const float4*)noise;
    const int threads = 256;                               // 8 warps = 16 rows/block
    const int blocks  = N_NODES / 16;                      // 10000

    // layer 0: split tables; xi_adj = item_emb - USER_LIM (pointer only formed)
    k_spmm<0, true><<<blocks, threads>>>((const float4*)user_emb,
                                   (const float4*)item_emb - (size_t)USER_LIM,
                                   noise4,
                                   nullptr, nullptr, ego1, out4);
    // layer 1: x = ego1 contiguous (no select, no second base)
    k_spmm<1, false><<<blocks, threads>>>((const float4*)ego1,
                                   nullptr,
                                   noise4 + (size_t)1 * N_NODES * D4,
                                   nullptr, nullptr, ego2, out4);
    // layer 2: x = ego2; epilogue writes final = (ego1+ego2+ego3)/3
    k_spmm<2, false><<<blocks, threads>>>((const float4*)ego2,
                                   nullptr,
                                   noise4 + (size_t)2 * N_NODES * D4,
                                   (const float4*)ego1, (const float4*)ego2,
                                   nullptr, out4);
}